// round 1
// baseline (speedup 1.0000x reference)
#include <cuda_runtime.h>

#define DIMSZ 512
#define NHEAD 8
#define HDIM  64
#define NB    4096
#define BSZ   32
#define SQ    128
#define BSROWS 4096
#define EPSLN 1e-5f

// scratch (allocation-free rule: __device__ globals)
__device__ float g_Q[BSROWS * DIMSZ];
__device__ float g_K[NB * DIMSZ];
__device__ float g_V[NB * DIMSZ];
__device__ float g_X[BSROWS * DIMSZ];

// ---------------------------------------------------------------------------
// SGEMM: C[m][n] = sum_k A[m*K+k] * Bw[n*K+k]   (both K-major, i.e. y = x @ W^T)
// BM=BN=128, BK=16, 256 threads, 8x8 micro-tile per thread.
// ---------------------------------------------------------------------------
__global__ __launch_bounds__(256) void sgemm_nt(
    const float* __restrict__ A, const float* __restrict__ Bw,
    float* __restrict__ C, int M, int N, int K)
{
    __shared__ float As[16][128];
    __shared__ float Bs[16][128];
    const int tid = threadIdx.x;
    const int tx = tid & 15, ty = tid >> 4;
    const int bm = blockIdx.y * 128, bn = blockIdx.x * 128;

    float acc[8][8];
#pragma unroll
    for (int i = 0; i < 8; i++)
#pragma unroll
        for (int j = 0; j < 8; j++) acc[i][j] = 0.f;

    for (int kt = 0; kt < K; kt += 16) {
#pragma unroll
        for (int i = 0; i < 2; i++) {
            int f = tid * 2 + i;          // 0..511
            int row = f >> 2;             // 0..127
            int kc = (f & 3) << 2;        // 0,4,8,12
            float4 va = *(const float4*)(A + (size_t)(bm + row) * K + kt + kc);
            As[kc + 0][row] = va.x; As[kc + 1][row] = va.y;
            As[kc + 2][row] = va.z; As[kc + 3][row] = va.w;
            float4 vb = *(const float4*)(Bw + (size_t)(bn + row) * K + kt + kc);
            Bs[kc + 0][row] = vb.x; Bs[kc + 1][row] = vb.y;
            Bs[kc + 2][row] = vb.z; Bs[kc + 3][row] = vb.w;
        }
        __syncthreads();
#pragma unroll
        for (int kk = 0; kk < 16; kk++) {
            float a[8], b[8];
            *(float4*)&a[0] = *(const float4*)&As[kk][ty * 8];
            *(float4*)&a[4] = *(const float4*)&As[kk][ty * 8 + 4];
            *(float4*)&b[0] = *(const float4*)&Bs[kk][tx * 8];
            *(float4*)&b[4] = *(const float4*)&Bs[kk][tx * 8 + 4];
#pragma unroll
            for (int i = 0; i < 8; i++)
#pragma unroll
                for (int j = 0; j < 8; j++)
                    acc[i][j] = fmaf(a[i], b[j], acc[i][j]);
        }
        __syncthreads();
    }
#pragma unroll
    for (int i = 0; i < 8; i++) {
        float* cp = C + (size_t)(bm + ty * 8 + i) * N + bn + tx * 8;
        float4 s0 = make_float4(acc[i][0], acc[i][1], acc[i][2], acc[i][3]);
        float4 s1 = make_float4(acc[i][4], acc[i][5], acc[i][6], acc[i][7]);
        *(float4*)cp = s0;
        *(float4*)(cp + 4) = s1;
    }
}

// ---------------------------------------------------------------------------
// Per-head layernorm over HD=64 elements, in-place. One warp per (row, head).
// out = (ln(x)*g + b) * scale
// ---------------------------------------------------------------------------
__global__ __launch_bounds__(256) void ln_heads(
    float* __restrict__ X, const float* __restrict__ g,
    const float* __restrict__ bb, float scale)
{
    int row = blockIdx.x;
    int hh = threadIdx.x >> 5;
    int lane = threadIdx.x & 31;
    float* p = X + (size_t)row * DIMSZ + hh * HDIM;
    float x0 = p[lane], x1 = p[lane + 32];
    float s = x0 + x1;
#pragma unroll
    for (int off = 16; off; off >>= 1) s += __shfl_xor_sync(0xffffffffu, s, off);
    float m = s * (1.f / 64.f);
    float d0 = x0 - m, d1 = x1 - m;
    float v = d0 * d0 + d1 * d1;
#pragma unroll
    for (int off = 16; off; off >>= 1) v += __shfl_xor_sync(0xffffffffu, v, off);
    float r = rsqrtf(v * (1.f / 64.f) + EPSLN);
    p[lane]      = (d0 * r * g[lane]      + bb[lane])      * scale;
    p[lane + 32] = (d1 * r * g[lane + 32] + bb[lane + 32]) * scale;
}

// ---------------------------------------------------------------------------
// Full-row layernorm over D=512, in-place. One warp per row (8 warps/block).
// ---------------------------------------------------------------------------
__global__ __launch_bounds__(256) void ln_full(
    float* __restrict__ X, const float* __restrict__ g, const float* __restrict__ bb)
{
    int row = blockIdx.x * 8 + (threadIdx.x >> 5);
    int lane = threadIdx.x & 31;
    float* p = X + (size_t)row * DIMSZ;
    float4 x[4];
    float s = 0.f;
#pragma unroll
    for (int q = 0; q < 4; q++) {
        x[q] = *(const float4*)(p + lane * 4 + q * 128);
        s += x[q].x + x[q].y + x[q].z + x[q].w;
    }
#pragma unroll
    for (int off = 16; off; off >>= 1) s += __shfl_xor_sync(0xffffffffu, s, off);
    float m = s * (1.f / 512.f);
    float v = 0.f;
#pragma unroll
    for (int q = 0; q < 4; q++) {
        x[q].x -= m; x[q].y -= m; x[q].z -= m; x[q].w -= m;
        v += x[q].x * x[q].x + x[q].y * x[q].y + x[q].z * x[q].z + x[q].w * x[q].w;
    }
#pragma unroll
    for (int off = 16; off; off >>= 1) v += __shfl_xor_sync(0xffffffffu, v, off);
    float r = rsqrtf(v * (1.f / 512.f) + EPSLN);
#pragma unroll
    for (int q = 0; q < 4; q++) {
        int c = lane * 4 + q * 128;
        float4 gg = *(const float4*)(g + c);
        float4 bv = *(const float4*)(bb + c);
        float4 o;
        o.x = x[q].x * r * gg.x + bv.x;
        o.y = x[q].y * r * gg.y + bv.y;
        o.z = x[q].z * r * gg.z + bv.z;
        o.w = x[q].w * r * gg.w + bv.w;
        *(float4*)(p + c) = o;
    }
}

// ---------------------------------------------------------------------------
// Fused flash attention (online softmax). One block per (b,h).
// 256 threads (16x16). S-tile = 128 queries x 64 keys per chunk.
// Thread (ty,tx) owns rows ty*8..+7, score cols tx*4..+3, O cols tx*4..+3.
// ---------------------------------------------------------------------------
#define QS_STR 132
#define KS_STR 68
#define PS_STR 132
#define ATTN_SMEM ((64*QS_STR + 64*KS_STR + 64*KS_STR + 64*PS_STR) * 4)

__device__ __forceinline__ float redmax16(float v) {
    v = fmaxf(v, __shfl_xor_sync(0xffffffffu, v, 1, 16));
    v = fmaxf(v, __shfl_xor_sync(0xffffffffu, v, 2, 16));
    v = fmaxf(v, __shfl_xor_sync(0xffffffffu, v, 4, 16));
    v = fmaxf(v, __shfl_xor_sync(0xffffffffu, v, 8, 16));
    return v;
}
__device__ __forceinline__ float redsum16(float v) {
    v += __shfl_xor_sync(0xffffffffu, v, 1, 16);
    v += __shfl_xor_sync(0xffffffffu, v, 2, 16);
    v += __shfl_xor_sync(0xffffffffu, v, 4, 16);
    v += __shfl_xor_sync(0xffffffffu, v, 8, 16);
    return v;
}

__global__ __launch_bounds__(256) void attn_kernel(
    const float* __restrict__ Q, const float* __restrict__ Kb,
    const float* __restrict__ Vb, float* __restrict__ Xo)
{
    extern __shared__ float sm[];
    float* Qs = sm;                       // [64][QS_STR] d-major: Qs[d][r]
    float* Ks = Qs + 64 * QS_STR;         // [64][KS_STR] d-major: Ks[d][j]
    float* Vs = Ks + 64 * KS_STR;         // [64][KS_STR] j-major: Vs[j][c]
    float* Ps = Vs + 64 * KS_STR;         // [64][PS_STR] j-major: Ps[j][r]

    const int bh = blockIdx.x;
    const int b = bh >> 3, h = bh & 7;
    const int tid = threadIdx.x;
    const int tx = tid & 15, ty = tid >> 4;
    const float* qbase = Q + (size_t)b * SQ * DIMSZ + h * HDIM;
    const float* kbase = Kb + h * HDIM;
    const float* vbase = Vb + h * HDIM;

    // load Q tile transposed into Qs[d][r]
#pragma unroll
    for (int i = 0; i < 8; i++) {
        int f = tid + i * 256;            // 0..2047
        int row = f >> 4;                 // 0..127
        int dc = (f & 15) << 2;           // 0..60
        float4 v = *(const float4*)(qbase + (size_t)row * DIMSZ + dc);
        Qs[(dc + 0) * QS_STR + row] = v.x;
        Qs[(dc + 1) * QS_STR + row] = v.y;
        Qs[(dc + 2) * QS_STR + row] = v.z;
        Qs[(dc + 3) * QS_STR + row] = v.w;
    }

    float m_run[8], l_run[8], o[8][4];
#pragma unroll
    for (int i = 0; i < 8; i++) {
        m_run[i] = -1e30f; l_run[i] = 0.f;
        o[i][0] = o[i][1] = o[i][2] = o[i][3] = 0.f;
    }

    for (int n0 = 0; n0 < NB; n0 += 64) {
        __syncthreads();   // previous AV done (and Q tile visible on first iter)
        // load K chunk (transposed) and V chunk (natural)
#pragma unroll
        for (int i = 0; i < 4; i++) {
            int f = tid + i * 256;        // 0..1023
            int j = f >> 4;               // 0..63
            int dc = (f & 15) << 2;
            float4 kv = *(const float4*)(kbase + (size_t)(n0 + j) * DIMSZ + dc);
            Ks[(dc + 0) * KS_STR + j] = kv.x;
            Ks[(dc + 1) * KS_STR + j] = kv.y;
            Ks[(dc + 2) * KS_STR + j] = kv.z;
            Ks[(dc + 3) * KS_STR + j] = kv.w;
            float4 vv = *(const float4*)(vbase + (size_t)(n0 + j) * DIMSZ + dc);
            *(float4*)&Vs[j * KS_STR + dc] = vv;
        }
        __syncthreads();

        // scores s[8][4] = Q[rows] . K[cols]
        float s[8][4];
#pragma unroll
        for (int i = 0; i < 8; i++) s[i][0] = s[i][1] = s[i][2] = s[i][3] = 0.f;
#pragma unroll 8
        for (int d = 0; d < 64; d++) {
            float a[8];
            *(float4*)&a[0] = *(const float4*)&Qs[d * QS_STR + ty * 8];
            *(float4*)&a[4] = *(const float4*)&Qs[d * QS_STR + ty * 8 + 4];
            float4 kf = *(const float4*)&Ks[d * KS_STR + tx * 4];
#pragma unroll
            for (int i = 0; i < 8; i++) {
                s[i][0] = fmaf(a[i], kf.x, s[i][0]);
                s[i][1] = fmaf(a[i], kf.y, s[i][1]);
                s[i][2] = fmaf(a[i], kf.z, s[i][2]);
                s[i][3] = fmaf(a[i], kf.w, s[i][3]);
            }
        }

        // online softmax per row; write p to Ps (j-major)
#pragma unroll
        for (int i = 0; i < 8; i++) {
            float cm = fmaxf(fmaxf(s[i][0], s[i][1]), fmaxf(s[i][2], s[i][3]));
            cm = redmax16(cm);
            float mn = fmaxf(m_run[i], cm);
            float al = __expf(m_run[i] - mn);
            float rs = 0.f;
#pragma unroll
            for (int c = 0; c < 4; c++) { s[i][c] = __expf(s[i][c] - mn); rs += s[i][c]; }
            rs = redsum16(rs);
            l_run[i] = l_run[i] * al + rs;
            m_run[i] = mn;
#pragma unroll
            for (int c = 0; c < 4; c++) {
                o[i][c] *= al;
                Ps[(tx * 4 + c) * PS_STR + ty * 8 + i] = s[i][c];
            }
        }
        __syncthreads();

        // O += P @ V
#pragma unroll 4
        for (int j = 0; j < 64; j++) {
            float p[8];
            *(float4*)&p[0] = *(const float4*)&Ps[j * PS_STR + ty * 8];
            *(float4*)&p[4] = *(const float4*)&Ps[j * PS_STR + ty * 8 + 4];
            float4 v4 = *(const float4*)&Vs[j * KS_STR + tx * 4];
#pragma unroll
            for (int i = 0; i < 8; i++) {
                o[i][0] = fmaf(p[i], v4.x, o[i][0]);
                o[i][1] = fmaf(p[i], v4.y, o[i][1]);
                o[i][2] = fmaf(p[i], v4.z, o[i][2]);
                o[i][3] = fmaf(p[i], v4.w, o[i][3]);
            }
        }
    }

    // epilogue: normalize and write (B,S,H,HD) -> (bs, D) layout
#pragma unroll
    for (int i = 0; i < 8; i++) {
        float inv = 1.f / l_run[i];
        int row = b * SQ + ty * 8 + i;
        float4 st = make_float4(o[i][0] * inv, o[i][1] * inv, o[i][2] * inv, o[i][3] * inv);
        *(float4*)(Xo + (size_t)row * DIMSZ + h * HDIM + tx * 4) = st;
    }
}

// ---------------------------------------------------------------------------
extern "C" void kernel_launch(void* const* d_in, const int* in_sizes, int n_in,
                              void* d_out, int out_size)
{
    const float* x_q   = (const float*)d_in[0];
    const float* x_k   = (const float*)d_in[1];
    const float* x_v   = (const float*)d_in[2];
    const float* Wq    = (const float*)d_in[3];
    const float* Wk    = (const float*)d_in[4];
    const float* Wv    = (const float*)d_in[5];
    const float* Wproj = (const float*)d_in[6];
    const float* qn_g  = (const float*)d_in[7];
    const float* qn_b  = (const float*)d_in[8];
    const float* kn_g  = (const float*)d_in[9];
    const float* kn_b  = (const float*)d_in[10];
    const float* n_g   = (const float*)d_in[11];
    const float* n_b   = (const float*)d_in[12];
    float* out = (float*)d_out;

    float *Qp, *Kp, *Vp, *Xp;
    cudaGetSymbolAddress((void**)&Qp, g_Q);
    cudaGetSymbolAddress((void**)&Kp, g_K);
    cudaGetSymbolAddress((void**)&Vp, g_V);
    cudaGetSymbolAddress((void**)&Xp, g_X);

    static bool attr_set = false;
    if (!attr_set) {
        cudaFuncSetAttribute(attn_kernel,
                             cudaFuncAttributeMaxDynamicSharedMemorySize, ATTN_SMEM);
        attr_set = true;
    }

    dim3 gemm_grid(DIMSZ / 128, BSROWS / 128);   // (4, 32)

    // projections
    sgemm_nt<<<gemm_grid, 256>>>(x_q, Wq, Qp, BSROWS, DIMSZ, DIMSZ);
    sgemm_nt<<<gemm_grid, 256>>>(x_k, Wk, Kp, NB, DIMSZ, DIMSZ);
    sgemm_nt<<<gemm_grid, 256>>>(x_v, Wv, Vp, NB, DIMSZ, DIMSZ);

    // per-head layernorms (q also scaled by HD^-0.5 = 0.125)
    ln_heads<<<BSROWS, 256>>>(Qp, qn_g, qn_b, 0.125f);
    ln_heads<<<NB, 256>>>(Kp, kn_g, kn_b, 1.0f);

    // fused attention
    attn_kernel<<<BSZ * NHEAD, 256, ATTN_SMEM>>>(Qp, Kp, Vp, Xp);

    // output layernorm + projection
    ln_full<<<BSROWS / 8, 256>>>(Xp, n_g, n_b);
    sgemm_nt<<<gemm_grid, 256>>>(Xp, Wproj, out, BSROWS, DIMSZ, DIMSZ);
}

// round 2
// speedup vs baseline: 2.1913x; 2.1913x over previous
#include <cuda_runtime.h>

#define DIMSZ 512
#define NHEAD 8
#define HDIM  64
#define NB    4096
#define BSZ   32
#define SQ    128
#define BSROWS 4096
#define EPSLN 1e-5f

// scratch (allocation-free rule: __device__ globals)
__device__ float g_Q[BSROWS * DIMSZ];
__device__ float g_K[NB * DIMSZ];
__device__ float g_V[NB * DIMSZ];
__device__ float g_X[BSROWS * DIMSZ];

// ---------------------------------------------------------------------------
// SGEMM: C[m][n] = sum_k A[m*K+k] * Bw[n*K+k]   (both K-major, i.e. y = x @ W^T)
// BM=BN=128, BK=16, 256 threads, 8x8 micro-tile per thread.  (fp32 this round)
// ---------------------------------------------------------------------------
__global__ __launch_bounds__(256) void sgemm_nt(
    const float* __restrict__ A, const float* __restrict__ Bw,
    float* __restrict__ C, int M, int N, int K)
{
    __shared__ float As[16][128];
    __shared__ float Bs[16][128];
    const int tid = threadIdx.x;
    const int tx = tid & 15, ty = tid >> 4;
    const int bm = blockIdx.y * 128, bn = blockIdx.x * 128;

    float acc[8][8];
#pragma unroll
    for (int i = 0; i < 8; i++)
#pragma unroll
        for (int j = 0; j < 8; j++) acc[i][j] = 0.f;

    for (int kt = 0; kt < K; kt += 16) {
#pragma unroll
        for (int i = 0; i < 2; i++) {
            int f = tid * 2 + i;
            int row = f >> 2;
            int kc = (f & 3) << 2;
            float4 va = *(const float4*)(A + (size_t)(bm + row) * K + kt + kc);
            As[kc + 0][row] = va.x; As[kc + 1][row] = va.y;
            As[kc + 2][row] = va.z; As[kc + 3][row] = va.w;
            float4 vb = *(const float4*)(Bw + (size_t)(bn + row) * K + kt + kc);
            Bs[kc + 0][row] = vb.x; Bs[kc + 1][row] = vb.y;
            Bs[kc + 2][row] = vb.z; Bs[kc + 3][row] = vb.w;
        }
        __syncthreads();
#pragma unroll
        for (int kk = 0; kk < 16; kk++) {
            float a[8], b[8];
            *(float4*)&a[0] = *(const float4*)&As[kk][ty * 8];
            *(float4*)&a[4] = *(const float4*)&As[kk][ty * 8 + 4];
            *(float4*)&b[0] = *(const float4*)&Bs[kk][tx * 8];
            *(float4*)&b[4] = *(const float4*)&Bs[kk][tx * 8 + 4];
#pragma unroll
            for (int i = 0; i < 8; i++)
#pragma unroll
                for (int j = 0; j < 8; j++)
                    acc[i][j] = fmaf(a[i], b[j], acc[i][j]);
        }
        __syncthreads();
    }
#pragma unroll
    for (int i = 0; i < 8; i++) {
        float* cp = C + (size_t)(bm + ty * 8 + i) * N + bn + tx * 8;
        *(float4*)cp = make_float4(acc[i][0], acc[i][1], acc[i][2], acc[i][3]);
        *(float4*)(cp + 4) = make_float4(acc[i][4], acc[i][5], acc[i][6], acc[i][7]);
    }
}

// ---------------------------------------------------------------------------
// Per-head layernorm over HD=64, in-place. One warp per (row, head).
// ---------------------------------------------------------------------------
__global__ __launch_bounds__(256) void ln_heads(
    float* __restrict__ X, const float* __restrict__ g,
    const float* __restrict__ bb, float scale)
{
    int row = blockIdx.x;
    int hh = threadIdx.x >> 5;
    int lane = threadIdx.x & 31;
    float* p = X + (size_t)row * DIMSZ + hh * HDIM;
    float x0 = p[lane], x1 = p[lane + 32];
    float s = x0 + x1;
#pragma unroll
    for (int off = 16; off; off >>= 1) s += __shfl_xor_sync(0xffffffffu, s, off);
    float m = s * (1.f / 64.f);
    float d0 = x0 - m, d1 = x1 - m;
    float v = d0 * d0 + d1 * d1;
#pragma unroll
    for (int off = 16; off; off >>= 1) v += __shfl_xor_sync(0xffffffffu, v, off);
    float r = rsqrtf(v * (1.f / 64.f) + EPSLN);
    p[lane]      = (d0 * r * g[lane]      + bb[lane])      * scale;
    p[lane + 32] = (d1 * r * g[lane + 32] + bb[lane + 32]) * scale;
}

// ---------------------------------------------------------------------------
// Full-row layernorm over D=512, in-place. One warp per row.
// ---------------------------------------------------------------------------
__global__ __launch_bounds__(256) void ln_full(
    float* __restrict__ X, const float* __restrict__ g, const float* __restrict__ bb)
{
    int row = blockIdx.x * 8 + (threadIdx.x >> 5);
    int lane = threadIdx.x & 31;
    float* p = X + (size_t)row * DIMSZ;
    float4 x[4];
    float s = 0.f;
#pragma unroll
    for (int q = 0; q < 4; q++) {
        x[q] = *(const float4*)(p + lane * 4 + q * 128);
        s += x[q].x + x[q].y + x[q].z + x[q].w;
    }
#pragma unroll
    for (int off = 16; off; off >>= 1) s += __shfl_xor_sync(0xffffffffu, s, off);
    float m = s * (1.f / 512.f);
    float v = 0.f;
#pragma unroll
    for (int q = 0; q < 4; q++) {
        x[q].x -= m; x[q].y -= m; x[q].z -= m; x[q].w -= m;
        v += x[q].x * x[q].x + x[q].y * x[q].y + x[q].z * x[q].z + x[q].w * x[q].w;
    }
#pragma unroll
    for (int off = 16; off; off >>= 1) v += __shfl_xor_sync(0xffffffffu, v, off);
    float r = rsqrtf(v * (1.f / 512.f) + EPSLN);
#pragma unroll
    for (int q = 0; q < 4; q++) {
        int c = lane * 4 + q * 128;
        float4 gg = *(const float4*)(g + c);
        float4 bv = *(const float4*)(bb + c);
        float4 o;
        o.x = x[q].x * r * gg.x + bv.x;
        o.y = x[q].y * r * gg.y + bv.y;
        o.z = x[q].z * r * gg.z + bv.z;
        o.w = x[q].w * r * gg.w + bv.w;
        *(float4*)(p + c) = o;
    }
}

// ---------------------------------------------------------------------------
// tf32 helpers
// ---------------------------------------------------------------------------
__device__ __forceinline__ unsigned tf32_of(float f) {
    unsigned u;
    asm("cvt.rna.tf32.f32 %0, %1;" : "=r"(u) : "f"(f));
    return u;
}
__device__ __forceinline__ void mma_tf32(
    float& c0, float& c1, float& c2, float& c3,
    unsigned a0, unsigned a1, unsigned a2, unsigned a3,
    unsigned b0, unsigned b1)
{
    asm volatile(
        "mma.sync.aligned.m16n8k8.row.col.f32.tf32.tf32.f32 "
        "{%0,%1,%2,%3}, {%4,%5,%6,%7}, {%8,%9}, {%0,%1,%2,%3};"
        : "+f"(c0), "+f"(c1), "+f"(c2), "+f"(c3)
        : "r"(a0), "r"(a1), "r"(a2), "r"(a3), "r"(b0), "r"(b1));
}

// ---------------------------------------------------------------------------
// Fused flash attention, tf32 tensor cores.
// One block per (b,h). 256 threads = 8 warps, 16 query rows per warp.
// Key chunks of 64. Q lives in registers as A-fragments.
// smem: Ks[64][68] (key-major), Vs[64][72], Ps[8 warps][16][68].
// ---------------------------------------------------------------------------
#define KSTR 68
#define VSTR 72
#define PSTR 68
#define ATTN_SMEM ((64 * KSTR + 64 * VSTR + 8 * 16 * PSTR) * 4)

__global__ __launch_bounds__(256, 2) void attn_mma(
    const float* __restrict__ Q, const float* __restrict__ Kb,
    const float* __restrict__ Vb, float* __restrict__ Xo)
{
    extern __shared__ float sm[];
    float* Ks = sm;                       // [key][dim] stride KSTR
    float* Vs = Ks + 64 * KSTR;           // [key][dim] stride VSTR
    float* Ps = Vs + 64 * VSTR;           // per-warp [row16][key64] stride PSTR

    const int bh = blockIdx.x;
    const int b = bh >> 3, h = bh & 7;
    const int tid = threadIdx.x;
    const int w = tid >> 5, lane = tid & 31;
    const int q4 = lane & 3, r4 = lane >> 2;
    float* Pw = Ps + w * 16 * PSTR;

    const float* kbase = Kb + h * HDIM;
    const float* vbase = Vb + h * HDIM;

    // Q fragments (warp rows w*16 + r4, w*16 + r4 + 8), converted to tf32
    unsigned qa[8][4];
    {
        const float* q0 = Q + (size_t)(b * SQ + w * 16 + r4) * DIMSZ + h * HDIM;
        const float* q1 = q0 + 8 * DIMSZ;
#pragma unroll
        for (int kk = 0; kk < 8; kk++) {
            int col = kk * 8 + q4;
            qa[kk][0] = tf32_of(q0[col]);
            qa[kk][1] = tf32_of(q1[col]);
            qa[kk][2] = tf32_of(q0[col + 4]);
            qa[kk][3] = tf32_of(q1[col + 4]);
        }
    }

    float mA = -1e30f, mB = -1e30f, lA = 0.f, lB = 0.f;
    float o[8][4];
#pragma unroll
    for (int dt = 0; dt < 8; dt++)
        o[dt][0] = o[dt][1] = o[dt][2] = o[dt][3] = 0.f;

    for (int n0 = 0; n0 < NB; n0 += 64) {
        __syncthreads();   // prior iteration's smem reads complete
        // fill K/V chunk (tf32-rounded)
#pragma unroll
        for (int i = 0; i < 4; i++) {
            int f = tid + i * 256;        // 0..1023
            int j = f >> 4;               // key 0..63
            int dc = (f & 15) << 2;       // dim 0..60
            float4 kv = *(const float4*)(kbase + (size_t)(n0 + j) * DIMSZ + dc);
            float4 vv = *(const float4*)(vbase + (size_t)(n0 + j) * DIMSZ + dc);
            float* kp = Ks + j * KSTR + dc;
            kp[0] = __uint_as_float(tf32_of(kv.x));
            kp[1] = __uint_as_float(tf32_of(kv.y));
            kp[2] = __uint_as_float(tf32_of(kv.z));
            kp[3] = __uint_as_float(tf32_of(kv.w));
            float* vp = Vs + j * VSTR + dc;
            vp[0] = __uint_as_float(tf32_of(vv.x));
            vp[1] = __uint_as_float(tf32_of(vv.y));
            vp[2] = __uint_as_float(tf32_of(vv.z));
            vp[3] = __uint_as_float(tf32_of(vv.w));
        }
        __syncthreads();

        // ---- scores: S[16x64] = Q @ K^T (per warp) ----
        float s[8][4];
#pragma unroll
        for (int nt = 0; nt < 8; nt++)
            s[nt][0] = s[nt][1] = s[nt][2] = s[nt][3] = 0.f;
#pragma unroll
        for (int nt = 0; nt < 8; nt++) {
            const float* kr = Ks + (nt * 8 + r4) * KSTR + q4;
#pragma unroll
            for (int kk = 0; kk < 8; kk++) {
                unsigned b0 = __float_as_uint(kr[kk * 8]);
                unsigned b1 = __float_as_uint(kr[kk * 8 + 4]);
                mma_tf32(s[nt][0], s[nt][1], s[nt][2], s[nt][3],
                         qa[kk][0], qa[kk][1], qa[kk][2], qa[kk][3], b0, b1);
            }
        }

        // ---- online softmax (rows rA = r4, rB = r4+8 within warp tile) ----
        float cmA = -1e30f, cmB = -1e30f;
#pragma unroll
        for (int nt = 0; nt < 8; nt++) {
            cmA = fmaxf(cmA, fmaxf(s[nt][0], s[nt][1]));
            cmB = fmaxf(cmB, fmaxf(s[nt][2], s[nt][3]));
        }
        cmA = fmaxf(cmA, __shfl_xor_sync(0xffffffffu, cmA, 1));
        cmA = fmaxf(cmA, __shfl_xor_sync(0xffffffffu, cmA, 2));
        cmB = fmaxf(cmB, __shfl_xor_sync(0xffffffffu, cmB, 1));
        cmB = fmaxf(cmB, __shfl_xor_sync(0xffffffffu, cmB, 2));
        float mnA = fmaxf(mA, cmA), mnB = fmaxf(mB, cmB);
        float alA = __expf(mA - mnA), alB = __expf(mB - mnB);
        float suA = 0.f, suB = 0.f;
#pragma unroll
        for (int nt = 0; nt < 8; nt++) {
            float p0 = __expf(s[nt][0] - mnA);
            float p1 = __expf(s[nt][1] - mnA);
            float p2 = __expf(s[nt][2] - mnB);
            float p3 = __expf(s[nt][3] - mnB);
            suA += p0 + p1; suB += p2 + p3;
            float* pr = Pw + r4 * PSTR + nt * 8 + 2 * q4;
            pr[0] = __uint_as_float(tf32_of(p0));
            pr[1] = __uint_as_float(tf32_of(p1));
            pr += 8 * PSTR;
            pr[0] = __uint_as_float(tf32_of(p2));
            pr[1] = __uint_as_float(tf32_of(p3));
        }
        suA += __shfl_xor_sync(0xffffffffu, suA, 1);
        suA += __shfl_xor_sync(0xffffffffu, suA, 2);
        suB += __shfl_xor_sync(0xffffffffu, suB, 1);
        suB += __shfl_xor_sync(0xffffffffu, suB, 2);
        lA = lA * alA + suA;
        lB = lB * alB + suB;
        mA = mnA; mB = mnB;
#pragma unroll
        for (int dt = 0; dt < 8; dt++) {
            o[dt][0] *= alA; o[dt][1] *= alA;
            o[dt][2] *= alB; o[dt][3] *= alB;
        }
        __syncwarp();   // P visible across warp lanes

        // ---- O += P @ V ----
#pragma unroll
        for (int kk = 0; kk < 8; kk++) {
            const float* pr = Pw + r4 * PSTR + kk * 8 + q4;
            unsigned a0 = __float_as_uint(pr[0]);
            unsigned a1 = __float_as_uint(pr[8 * PSTR]);
            unsigned a2 = __float_as_uint(pr[4]);
            unsigned a3 = __float_as_uint(pr[8 * PSTR + 4]);
            const float* vr = Vs + (kk * 8 + q4) * VSTR + r4;
#pragma unroll
            for (int dt = 0; dt < 8; dt++) {
                unsigned b0 = __float_as_uint(vr[dt * 8]);
                unsigned b1 = __float_as_uint(vr[4 * VSTR + dt * 8]);
                mma_tf32(o[dt][0], o[dt][1], o[dt][2], o[dt][3],
                         a0, a1, a2, a3, b0, b1);
            }
        }
    }

    // epilogue: normalize, write to (bs, D) layout
    float ivA = 1.f / lA, ivB = 1.f / lB;
    int rowA = b * SQ + w * 16 + r4;
    float* xoA = Xo + (size_t)rowA * DIMSZ + h * HDIM + 2 * q4;
    float* xoB = xoA + 8 * DIMSZ;
#pragma unroll
    for (int dt = 0; dt < 8; dt++) {
        *(float2*)(xoA + dt * 8) = make_float2(o[dt][0] * ivA, o[dt][1] * ivA);
        *(float2*)(xoB + dt * 8) = make_float2(o[dt][2] * ivB, o[dt][3] * ivB);
    }
}

// ---------------------------------------------------------------------------
extern "C" void kernel_launch(void* const* d_in, const int* in_sizes, int n_in,
                              void* d_out, int out_size)
{
    const float* x_q   = (const float*)d_in[0];
    const float* x_k   = (const float*)d_in[1];
    const float* x_v   = (const float*)d_in[2];
    const float* Wq    = (const float*)d_in[3];
    const float* Wk    = (const float*)d_in[4];
    const float* Wv    = (const float*)d_in[5];
    const float* Wproj = (const float*)d_in[6];
    const float* qn_g  = (const float*)d_in[7];
    const float* qn_b  = (const float*)d_in[8];
    const float* kn_g  = (const float*)d_in[9];
    const float* kn_b  = (const float*)d_in[10];
    const float* n_g   = (const float*)d_in[11];
    const float* n_b   = (const float*)d_in[12];
    float* out = (float*)d_out;

    float *Qp, *Kp, *Vp, *Xp;
    cudaGetSymbolAddress((void**)&Qp, g_Q);
    cudaGetSymbolAddress((void**)&Kp, g_K);
    cudaGetSymbolAddress((void**)&Vp, g_V);
    cudaGetSymbolAddress((void**)&Xp, g_X);

    static bool attr_set = false;
    if (!attr_set) {
        cudaFuncSetAttribute(attn_mma,
                             cudaFuncAttributeMaxDynamicSharedMemorySize, ATTN_SMEM);
        attr_set = true;
    }

    dim3 gemm_grid(DIMSZ / 128, BSROWS / 128);   // (4, 32)

    // projections (fp32)
    sgemm_nt<<<gemm_grid, 256>>>(x_q, Wq, Qp, BSROWS, DIMSZ, DIMSZ);
    sgemm_nt<<<gemm_grid, 256>>>(x_k, Wk, Kp, NB, DIMSZ, DIMSZ);
    sgemm_nt<<<gemm_grid, 256>>>(x_v, Wv, Vp, NB, DIMSZ, DIMSZ);

    // per-head layernorms (q also scaled by HD^-0.5 = 0.125)
    ln_heads<<<BSROWS, 256>>>(Qp, qn_g, qn_b, 0.125f);
    ln_heads<<<NB, 256>>>(Kp, kn_g, kn_b, 1.0f);

    // fused attention (tf32 tensor cores)
    attn_mma<<<BSZ * NHEAD, 256, ATTN_SMEM>>>(Qp, Kp, Vp, Xp);

    // output layernorm + projection
    ln_full<<<BSROWS / 8, 256>>>(Xp, n_g, n_b);
    sgemm_nt<<<gemm_grid, 256>>>(Xp, Wproj, out, BSROWS, DIMSZ, DIMSZ);
}

// round 3
// speedup vs baseline: 3.2248x; 1.4716x over previous
#include <cuda_runtime.h>

#define DIMSZ 512
#define NHEAD 8
#define HDIM  64
#define NB    4096
#define BSZ   32
#define SQ    128
#define BSROWS 4096
#define EPSLN 1e-5f

// scratch (allocation-free rule: __device__ globals)
__device__ float g_Q[BSROWS * DIMSZ];
__device__ float g_K[NB * DIMSZ];
__device__ float g_V[NB * DIMSZ];
__device__ float g_X[BSROWS * DIMSZ];

// ---------------------------------------------------------------------------
// tf32 helpers
// ---------------------------------------------------------------------------
__device__ __forceinline__ unsigned tf32_of(float f) {
    unsigned u;
    asm("cvt.rna.tf32.f32 %0, %1;" : "=r"(u) : "f"(f));
    return u;
}
__device__ __forceinline__ float tf32f(float f) {
    return __uint_as_float(tf32_of(f));
}
__device__ __forceinline__ void mma_tf32(
    float& c0, float& c1, float& c2, float& c3,
    unsigned a0, unsigned a1, unsigned a2, unsigned a3,
    unsigned b0, unsigned b1)
{
    asm volatile(
        "mma.sync.aligned.m16n8k8.row.col.f32.tf32.tf32.f32 "
        "{%0,%1,%2,%3}, {%4,%5,%6,%7}, {%8,%9}, {%0,%1,%2,%3};"
        : "+f"(c0), "+f"(c1), "+f"(c2), "+f"(c3)
        : "r"(a0), "r"(a1), "r"(a2), "r"(a3), "r"(b0), "r"(b1));
}

// ---------------------------------------------------------------------------
// tf32 GEMM: C[m][n] = sum_k A[m][k] * Bw[n][k]  (y = x @ W^T), M=4096,N=512,K=512
// BM=128, BN=64, BK=32. 256 threads = 8 warps (4 m x 2 n), 32x32 warp tile.
// smem stride 36: conflict-free for both float4 STS and scalar fragment LDS.
// ---------------------------------------------------------------------------
#define GST 36

__global__ __launch_bounds__(256, 2) void gemm_tf32(
    const float* __restrict__ A, const float* __restrict__ Bw,
    float* __restrict__ C)
{
    __shared__ float As[128 * GST];
    __shared__ float Bs[64 * GST];
    const int tid = threadIdx.x;
    const int lane = tid & 31, w = tid >> 5;
    const int q4 = lane & 3, r4 = lane >> 2;
    const int wm = (w & 3) * 32;
    const int wn = (w >> 2) * 32;
    const int bm = blockIdx.y * 128;
    const int bn = blockIdx.x * 64;

    float acc[2][4][4];
#pragma unroll
    for (int mt = 0; mt < 2; mt++)
#pragma unroll
        for (int nt = 0; nt < 4; nt++)
#pragma unroll
            for (int c = 0; c < 4; c++) acc[mt][nt][c] = 0.f;

    for (int kt = 0; kt < DIMSZ; kt += 32) {
        __syncthreads();
#pragma unroll
        for (int i = 0; i < 4; i++) {
            int idx = tid + i * 256;          // 0..1023
            int row = idx >> 3;               // 0..127
            int kc = (idx & 7) << 2;          // 0..28
            float4 v = *(const float4*)(A + (size_t)(bm + row) * DIMSZ + kt + kc);
            float* p = As + row * GST + kc;
            p[0] = tf32f(v.x); p[1] = tf32f(v.y);
            p[2] = tf32f(v.z); p[3] = tf32f(v.w);
        }
#pragma unroll
        for (int i = 0; i < 2; i++) {
            int idx = tid + i * 256;          // 0..511
            int row = idx >> 3;               // 0..63
            int kc = (idx & 7) << 2;
            float4 v = *(const float4*)(Bw + (size_t)(bn + row) * DIMSZ + kt + kc);
            float* p = Bs + row * GST + kc;
            p[0] = tf32f(v.x); p[1] = tf32f(v.y);
            p[2] = tf32f(v.z); p[3] = tf32f(v.w);
        }
        __syncthreads();

#pragma unroll
        for (int ks = 0; ks < 4; ks++) {
            unsigned af[2][4], bf[4][2];
#pragma unroll
            for (int mt = 0; mt < 2; mt++) {
                const float* ap = As + (wm + mt * 16 + r4) * GST + ks * 8 + q4;
                af[mt][0] = __float_as_uint(ap[0]);
                af[mt][1] = __float_as_uint(ap[8 * GST]);
                af[mt][2] = __float_as_uint(ap[4]);
                af[mt][3] = __float_as_uint(ap[8 * GST + 4]);
            }
#pragma unroll
            for (int nt = 0; nt < 4; nt++) {
                const float* bp = Bs + (wn + nt * 8 + r4) * GST + ks * 8 + q4;
                bf[nt][0] = __float_as_uint(bp[0]);
                bf[nt][1] = __float_as_uint(bp[4]);
            }
#pragma unroll
            for (int mt = 0; mt < 2; mt++)
#pragma unroll
                for (int nt = 0; nt < 4; nt++)
                    mma_tf32(acc[mt][nt][0], acc[mt][nt][1], acc[mt][nt][2], acc[mt][nt][3],
                             af[mt][0], af[mt][1], af[mt][2], af[mt][3],
                             bf[nt][0], bf[nt][1]);
        }
    }

    // epilogue: c0=C[r4][2q4], c1=C[r4][2q4+1], c2=C[r4+8][2q4], c3=C[r4+8][2q4+1]
#pragma unroll
    for (int mt = 0; mt < 2; mt++) {
        int r0 = bm + wm + mt * 16 + r4;
#pragma unroll
        for (int nt = 0; nt < 4; nt++) {
            float* cp = C + (size_t)r0 * DIMSZ + bn + wn + nt * 8 + 2 * q4;
            *(float2*)cp = make_float2(acc[mt][nt][0], acc[mt][nt][1]);
            *(float2*)(cp + (size_t)8 * DIMSZ) = make_float2(acc[mt][nt][2], acc[mt][nt][3]);
        }
    }
}

// ---------------------------------------------------------------------------
// Per-head layernorm over HD=64, in-place. One warp per (row, head).
// ---------------------------------------------------------------------------
__global__ __launch_bounds__(256) void ln_heads(
    float* __restrict__ X, const float* __restrict__ g,
    const float* __restrict__ bb, float scale)
{
    int row = blockIdx.x;
    int hh = threadIdx.x >> 5;
    int lane = threadIdx.x & 31;
    float* p = X + (size_t)row * DIMSZ + hh * HDIM;
    float x0 = p[lane], x1 = p[lane + 32];
    float s = x0 + x1;
#pragma unroll
    for (int off = 16; off; off >>= 1) s += __shfl_xor_sync(0xffffffffu, s, off);
    float m = s * (1.f / 64.f);
    float d0 = x0 - m, d1 = x1 - m;
    float v = d0 * d0 + d1 * d1;
#pragma unroll
    for (int off = 16; off; off >>= 1) v += __shfl_xor_sync(0xffffffffu, v, off);
    float r = rsqrtf(v * (1.f / 64.f) + EPSLN);
    p[lane]      = (d0 * r * g[lane]      + bb[lane])      * scale;
    p[lane + 32] = (d1 * r * g[lane + 32] + bb[lane + 32]) * scale;
}

// ---------------------------------------------------------------------------
// Full-row layernorm over D=512, in-place. One warp per row.
// ---------------------------------------------------------------------------
__global__ __launch_bounds__(256) void ln_full(
    float* __restrict__ X, const float* __restrict__ g, const float* __restrict__ bb)
{
    int row = blockIdx.x * 8 + (threadIdx.x >> 5);
    int lane = threadIdx.x & 31;
    float* p = X + (size_t)row * DIMSZ;
    float4 x[4];
    float s = 0.f;
#pragma unroll
    for (int q = 0; q < 4; q++) {
        x[q] = *(const float4*)(p + lane * 4 + q * 128);
        s += x[q].x + x[q].y + x[q].z + x[q].w;
    }
#pragma unroll
    for (int off = 16; off; off >>= 1) s += __shfl_xor_sync(0xffffffffu, s, off);
    float m = s * (1.f / 512.f);
    float v = 0.f;
#pragma unroll
    for (int q = 0; q < 4; q++) {
        x[q].x -= m; x[q].y -= m; x[q].z -= m; x[q].w -= m;
        v += x[q].x * x[q].x + x[q].y * x[q].y + x[q].z * x[q].z + x[q].w * x[q].w;
    }
#pragma unroll
    for (int off = 16; off; off >>= 1) v += __shfl_xor_sync(0xffffffffu, v, off);
    float r = rsqrtf(v * (1.f / 512.f) + EPSLN);
#pragma unroll
    for (int q = 0; q < 4; q++) {
        int c = lane * 4 + q * 128;
        float4 gg = *(const float4*)(g + c);
        float4 bv = *(const float4*)(bb + c);
        float4 o;
        o.x = x[q].x * r * gg.x + bv.x;
        o.y = x[q].y * r * gg.y + bv.y;
        o.z = x[q].z * r * gg.z + bv.z;
        o.w = x[q].w * r * gg.w + bv.w;
        *(float4*)(p + c) = o;
    }
}

// ---------------------------------------------------------------------------
// Fused flash attention, tf32 tensor cores.
// One block per (b,h). 256 threads = 8 warps, 16 query rows per warp.
// ---------------------------------------------------------------------------
#define KSTR 68
#define VSTR 72
#define PSTR 68
#define ATTN_SMEM ((64 * KSTR + 64 * VSTR + 8 * 16 * PSTR) * 4)

__global__ __launch_bounds__(256, 2) void attn_mma(
    const float* __restrict__ Q, const float* __restrict__ Kb,
    const float* __restrict__ Vb, float* __restrict__ Xo)
{
    extern __shared__ float sm[];
    float* Ks = sm;                       // [key][dim] stride KSTR
    float* Vs = Ks + 64 * KSTR;           // [key][dim] stride VSTR
    float* Ps = Vs + 64 * VSTR;           // per-warp [row16][key64] stride PSTR

    const int bh = blockIdx.x;
    const int b = bh >> 3, h = bh & 7;
    const int tid = threadIdx.x;
    const int w = tid >> 5, lane = tid & 31;
    const int q4 = lane & 3, r4 = lane >> 2;
    float* Pw = Ps + w * 16 * PSTR;

    const float* kbase = Kb + h * HDIM;
    const float* vbase = Vb + h * HDIM;

    unsigned qa[8][4];
    {
        const float* q0 = Q + (size_t)(b * SQ + w * 16 + r4) * DIMSZ + h * HDIM;
        const float* q1 = q0 + 8 * DIMSZ;
#pragma unroll
        for (int kk = 0; kk < 8; kk++) {
            int col = kk * 8 + q4;
            qa[kk][0] = tf32_of(q0[col]);
            qa[kk][1] = tf32_of(q1[col]);
            qa[kk][2] = tf32_of(q0[col + 4]);
            qa[kk][3] = tf32_of(q1[col + 4]);
        }
    }

    float mA = -1e30f, mB = -1e30f, lA = 0.f, lB = 0.f;
    float o[8][4];
#pragma unroll
    for (int dt = 0; dt < 8; dt++)
        o[dt][0] = o[dt][1] = o[dt][2] = o[dt][3] = 0.f;

    for (int n0 = 0; n0 < NB; n0 += 64) {
        __syncthreads();
#pragma unroll
        for (int i = 0; i < 4; i++) {
            int f = tid + i * 256;
            int j = f >> 4;
            int dc = (f & 15) << 2;
            float4 kv = *(const float4*)(kbase + (size_t)(n0 + j) * DIMSZ + dc);
            float4 vv = *(const float4*)(vbase + (size_t)(n0 + j) * DIMSZ + dc);
            float* kp = Ks + j * KSTR + dc;
            kp[0] = tf32f(kv.x); kp[1] = tf32f(kv.y);
            kp[2] = tf32f(kv.z); kp[3] = tf32f(kv.w);
            float* vp = Vs + j * VSTR + dc;
            vp[0] = tf32f(vv.x); vp[1] = tf32f(vv.y);
            vp[2] = tf32f(vv.z); vp[3] = tf32f(vv.w);
        }
        __syncthreads();

        // scores
        float s[8][4];
#pragma unroll
        for (int nt = 0; nt < 8; nt++)
            s[nt][0] = s[nt][1] = s[nt][2] = s[nt][3] = 0.f;
#pragma unroll
        for (int nt = 0; nt < 8; nt++) {
            const float* kr = Ks + (nt * 8 + r4) * KSTR + q4;
#pragma unroll
            for (int kk = 0; kk < 8; kk++) {
                unsigned b0 = __float_as_uint(kr[kk * 8]);
                unsigned b1 = __float_as_uint(kr[kk * 8 + 4]);
                mma_tf32(s[nt][0], s[nt][1], s[nt][2], s[nt][3],
                         qa[kk][0], qa[kk][1], qa[kk][2], qa[kk][3], b0, b1);
            }
        }

        // online softmax
        float cmA = -1e30f, cmB = -1e30f;
#pragma unroll
        for (int nt = 0; nt < 8; nt++) {
            cmA = fmaxf(cmA, fmaxf(s[nt][0], s[nt][1]));
            cmB = fmaxf(cmB, fmaxf(s[nt][2], s[nt][3]));
        }
        cmA = fmaxf(cmA, __shfl_xor_sync(0xffffffffu, cmA, 1));
        cmA = fmaxf(cmA, __shfl_xor_sync(0xffffffffu, cmA, 2));
        cmB = fmaxf(cmB, __shfl_xor_sync(0xffffffffu, cmB, 1));
        cmB = fmaxf(cmB, __shfl_xor_sync(0xffffffffu, cmB, 2));
        float mnA = fmaxf(mA, cmA), mnB = fmaxf(mB, cmB);
        float alA = __expf(mA - mnA), alB = __expf(mB - mnB);
        float suA = 0.f, suB = 0.f;
#pragma unroll
        for (int nt = 0; nt < 8; nt++) {
            float p0 = __expf(s[nt][0] - mnA);
            float p1 = __expf(s[nt][1] - mnA);
            float p2 = __expf(s[nt][2] - mnB);
            float p3 = __expf(s[nt][3] - mnB);
            suA += p0 + p1; suB += p2 + p3;
            float* pr = Pw + r4 * PSTR + nt * 8 + 2 * q4;
            pr[0] = tf32f(p0);
            pr[1] = tf32f(p1);
            pr += 8 * PSTR;
            pr[0] = tf32f(p2);
            pr[1] = tf32f(p3);
        }
        suA += __shfl_xor_sync(0xffffffffu, suA, 1);
        suA += __shfl_xor_sync(0xffffffffu, suA, 2);
        suB += __shfl_xor_sync(0xffffffffu, suB, 1);
        suB += __shfl_xor_sync(0xffffffffu, suB, 2);
        lA = lA * alA + suA;
        lB = lB * alB + suB;
        mA = mnA; mB = mnB;
#pragma unroll
        for (int dt = 0; dt < 8; dt++) {
            o[dt][0] *= alA; o[dt][1] *= alA;
            o[dt][2] *= alB; o[dt][3] *= alB;
        }
        __syncwarp();

        // O += P @ V
#pragma unroll
        for (int kk = 0; kk < 8; kk++) {
            const float* pr = Pw + r4 * PSTR + kk * 8 + q4;
            unsigned a0 = __float_as_uint(pr[0]);
            unsigned a1 = __float_as_uint(pr[8 * PSTR]);
            unsigned a2 = __float_as_uint(pr[4]);
            unsigned a3 = __float_as_uint(pr[8 * PSTR + 4]);
            const float* vr = Vs + (kk * 8 + q4) * VSTR + r4;
#pragma unroll
            for (int dt = 0; dt < 8; dt++) {
                unsigned b0 = __float_as_uint(vr[dt * 8]);
                unsigned b1 = __float_as_uint(vr[4 * VSTR + dt * 8]);
                mma_tf32(o[dt][0], o[dt][1], o[dt][2], o[dt][3],
                         a0, a1, a2, a3, b0, b1);
            }
        }
    }

    float ivA = 1.f / lA, ivB = 1.f / lB;
    int rowA = b * SQ + w * 16 + r4;
    float* xoA = Xo + (size_t)rowA * DIMSZ + h * HDIM + 2 * q4;
    float* xoB = xoA + 8 * DIMSZ;
#pragma unroll
    for (int dt = 0; dt < 8; dt++) {
        *(float2*)(xoA + dt * 8) = make_float2(o[dt][0] * ivA, o[dt][1] * ivA);
        *(float2*)(xoB + dt * 8) = make_float2(o[dt][2] * ivB, o[dt][3] * ivB);
    }
}

// ---------------------------------------------------------------------------
extern "C" void kernel_launch(void* const* d_in, const int* in_sizes, int n_in,
                              void* d_out, int out_size)
{
    const float* x_q   = (const float*)d_in[0];
    const float* x_k   = (const float*)d_in[1];
    const float* x_v   = (const float*)d_in[2];
    const float* Wq    = (const float*)d_in[3];
    const float* Wk    = (const float*)d_in[4];
    const float* Wv    = (const float*)d_in[5];
    const float* Wproj = (const float*)d_in[6];
    const float* qn_g  = (const float*)d_in[7];
    const float* qn_b  = (const float*)d_in[8];
    const float* kn_g  = (const float*)d_in[9];
    const float* kn_b  = (const float*)d_in[10];
    const float* n_g   = (const float*)d_in[11];
    const float* n_b   = (const float*)d_in[12];
    float* out = (float*)d_out;

    float *Qp, *Kp, *Vp, *Xp;
    cudaGetSymbolAddress((void**)&Qp, g_Q);
    cudaGetSymbolAddress((void**)&Kp, g_K);
    cudaGetSymbolAddress((void**)&Vp, g_V);
    cudaGetSymbolAddress((void**)&Xp, g_X);

    static bool attr_set = false;
    if (!attr_set) {
        cudaFuncSetAttribute(attn_mma,
                             cudaFuncAttributeMaxDynamicSharedMemorySize, ATTN_SMEM);
        attr_set = true;
    }

    dim3 gemm_grid(DIMSZ / 64, BSROWS / 128);    // (8, 32) = 256 blocks

    // projections (tf32 tensor cores)
    gemm_tf32<<<gemm_grid, 256>>>(x_q, Wq, Qp);
    gemm_tf32<<<gemm_grid, 256>>>(x_k, Wk, Kp);
    gemm_tf32<<<gemm_grid, 256>>>(x_v, Wv, Vp);

    // per-head layernorms (q also scaled by HD^-0.5 = 0.125)
    ln_heads<<<BSROWS, 256>>>(Qp, qn_g, qn_b, 0.125f);
    ln_heads<<<NB, 256>>>(Kp, kn_g, kn_b, 1.0f);

    // fused attention (tf32 tensor cores)
    attn_mma<<<BSZ * NHEAD, 256, ATTN_SMEM>>>(Qp, Kp, Vp, Xp);

    // output layernorm + projection
    ln_full<<<BSROWS / 8, 256>>>(Xp, n_g, n_b);
    gemm_tf32<<<gemm_grid, 256>>>(Xp, Wproj, out);
}